// round 1
// baseline (speedup 1.0000x reference)
#include <cuda_runtime.h>
#include <cstdint>

// Problem constants (N = 8192 ReLU nodes; matrices are (N+1)x(N+1)).
#define NN   8192
#define NP1  8193

// Output layout (tuple order, flattened, fp32):
//   conc_low : [0, N)
//   conc_up  : [N, 2N)
//   A_low    : [2N, 2N + NP1*NP1)           row-major
//   A_up     : [2N + NP1*NP1, 2N + 2*NP1*NP1)
//
// A_low: diag = diag_low, [N][N] = 1.
// A_up : diag = diag_up,  last row [N][0..N) = bias_up, [N][N] = 1.
// Everything else is zero -> bulk cudaMemsetAsync + tiny fixup kernel.

__global__ void relu_relax_fixup(const float* __restrict__ lower,
                                 const float* __restrict__ upper,
                                 const float* __restrict__ alphas,
                                 float* __restrict__ out) {
    const int i = blockIdx.x * blockDim.x + threadIdx.x;

    const size_t base_cl   = 0;
    const size_t base_cu   = (size_t)NN;
    const size_t base_Alow = (size_t)2 * NN;
    const size_t base_Aup  = base_Alow + (size_t)NP1 * (size_t)NP1;
    const size_t lastrow   = base_Aup + (size_t)NN * (size_t)NP1;  // A_up row N, col 0

    if (i < NN) {
        const float l  = lower[i];
        const float u  = upper[i];
        const float al = alphas[i];

        const float a        = fminf(fmaxf(al, 0.0f), 1.0f);
        const bool  active   = (u > 0.0f) && (l >= 0.0f);
        const bool  unstable = (u > 0.0f) && (l < 0.0f);

        const float denom = u - l;
        const float lam   = u / ((denom == 0.0f) ? 1.0f : denom);

        const float diag_low = active ? 1.0f : (unstable ? a   : 0.0f);
        const float diag_up  = active ? 1.0f : (unstable ? lam : 0.0f);
        const float bias_up  = unstable ? (-lam * l) : 0.0f;
        const float conc_low = active ? l : (unstable ? (a * l) : 0.0f);
        const float conc_up  = (u > 0.0f) ? u : 0.0f;

        // Coalesced vector writes
        out[base_cl + (size_t)i] = conc_low;
        out[base_cu + (size_t)i] = conc_up;
        out[lastrow + (size_t)i] = bias_up;

        // Diagonal scatter (stride NP1+1 elements)
        const size_t d = (size_t)i * (size_t)(NP1 + 1);
        out[base_Alow + d] = diag_low;
        out[base_Aup  + d] = diag_up;
    } else if (i == NN) {
        // A_low[N][N] = 1, A_up[N][N] = 1
        out[base_Alow + (size_t)NN * (size_t)NP1 + (size_t)NN] = 1.0f;
        out[lastrow + (size_t)NN] = 1.0f;
    }
}

extern "C" void kernel_launch(void* const* d_in, const int* in_sizes, int n_in,
                              void* d_out, int out_size) {
    const float* lower  = (const float*)d_in[0];
    const float* upper  = (const float*)d_in[1];
    const float* alphas = (const float*)d_in[2];
    float* out = (float*)d_out;

    // Bulk zero: graph-capturable memset node, runs at HBM write ceiling.
    cudaMemsetAsync(d_out, 0, (size_t)out_size * sizeof(float), 0);

    // Fixup: 8193 working threads write all nonzero entries.
    const int threads = 256;
    const int blocks  = (NP1 + threads - 1) / threads;
    relu_relax_fixup<<<blocks, threads>>>(lower, upper, alphas, out);
}